// round 5
// baseline (speedup 1.0000x reference)
#include <cuda_runtime.h>
#include <cstdint>
#include <math.h>

#define H_DIM 2048
#define I_DIM 4096
#define E_NUM 8
#define T_MAX 1024

// ---------------- scratch (__device__ globals: allocation-free) ----------------
__device__ float g_xs[T_MAX * H_DIM];
__device__ float g_gu[T_MAX * 2 * I_DIM];
__device__ float g_actS[T_MAX * I_DIM];
__device__ float g_actR[T_MAX * I_DIM];
__device__ int   g_eid[T_MAX];
__device__ int   g_perm[T_MAX];
__device__ int   g_off[E_NUM + 1];
__device__ float g_scores_scratch[E_NUM * T_MAX];

// ---------------- helpers ----------------
__device__ __forceinline__ float f2tf32(float x) {
    uint32_t u;
    asm("cvt.rna.tf32.f32 %0, %1;" : "=r"(u) : "f"(x));
    return __uint_as_float(u);
}

__device__ __forceinline__ void mma_tf32(float c[4],
                                         uint32_t a0, uint32_t a1, uint32_t a2, uint32_t a3,
                                         uint32_t b0, uint32_t b1) {
    asm volatile(
        "mma.sync.aligned.m16n8k8.row.col.f32.tf32.tf32.f32 "
        "{%0,%1,%2,%3}, {%4,%5,%6,%7}, {%8,%9}, {%0,%1,%2,%3};"
        : "+f"(c[0]), "+f"(c[1]), "+f"(c[2]), "+f"(c[3])
        : "r"(a0), "r"(a1), "r"(a2), "r"(a3), "r"(b0), "r"(b1));
}

// ---------------- 1) router ----------------
__global__ void router_kernel(const float* __restrict__ x, const float* __restrict__ rw,
                              float* __restrict__ scores_out, int T) {
    int t = blockIdx.x;
    int tid = threadIdx.x;
    __shared__ float s[256 * 8];
    __shared__ float sc_sh;

    float xv[8];
    float acc[8];
#pragma unroll
    for (int e = 0; e < 8; e++) acc[e] = 0.f;
#pragma unroll
    for (int j = 0; j < 8; j++) {
        int h = tid + j * 256;
        float v = x[(size_t)t * H_DIM + h];
        xv[j] = v;
        const float4* wp = (const float4*)(rw + (size_t)h * 8);
        float4 w0 = wp[0], w1 = wp[1];
        acc[0] += v * w0.x; acc[1] += v * w0.y; acc[2] += v * w0.z; acc[3] += v * w0.w;
        acc[4] += v * w1.x; acc[5] += v * w1.y; acc[6] += v * w1.z; acc[7] += v * w1.w;
    }
#pragma unroll
    for (int e = 0; e < 8; e++) s[tid * 8 + e] = acc[e];
    __syncthreads();
    for (int str = 128; str > 0; str >>= 1) {
        if (tid < str) {
#pragma unroll
            for (int e = 0; e < 8; e++) s[tid * 8 + e] += s[(tid + str) * 8 + e];
        }
        __syncthreads();
    }
    if (tid == 0) {
        int best = 0;
        float bv = s[0];
#pragma unroll
        for (int e = 1; e < 8; e++) {
            if (s[e] > bv) { bv = s[e]; best = e; }
        }
        float sc = 1.f / (1.f + expf(-bv));
        g_eid[t] = best;
#pragma unroll
        for (int e = 0; e < 8; e++)
            scores_out[(size_t)e * T + t] = (e == best) ? sc : 0.f;
        sc_sh = sc;
    }
    __syncthreads();
    float sc = sc_sh;
#pragma unroll
    for (int j = 0; j < 8; j++)
        g_xs[(size_t)t * H_DIM + tid + j * 256] = sc * xv[j];
}

// ---------------- 2) grouping ----------------
__global__ void group_kernel(int T) {
    int t = threadIdx.x;
    __shared__ int wcnt[32][8];
    __shared__ int woff[32][8];
    __shared__ int eoff[9];
    __shared__ int ecnt[8];
    if (t < 256) ((int*)wcnt)[t] = 0;
    __syncthreads();
    int e = (t < T) ? g_eid[t] : -1;
    unsigned mask = __match_any_sync(0xffffffffu, e);
    unsigned lanebit = 1u << (t & 31);
    int rank = __popc(mask & (lanebit - 1u));
    int w = t >> 5;
    if (e >= 0 && rank == 0) wcnt[w][e] = __popc(mask);
    __syncthreads();
    if (t < 8) {
        int run = 0;
        for (int ww = 0; ww < 32; ww++) { woff[ww][t] = run; run += wcnt[ww][t]; }
        ecnt[t] = run;
    }
    __syncthreads();
    if (t == 0) {
        int run = 0;
        for (int ee = 0; ee < 8; ee++) { eoff[ee] = run; run += ecnt[ee]; }
        eoff[8] = run;
    }
    __syncthreads();
    if (e >= 0) g_perm[eoff[e] + woff[w][e] + rank] = t;
    if (t < 9) g_off[t] = eoff[t];
}

// ---------------- 3) swiglu ----------------
__global__ void swiglu_kernel(const float* __restrict__ gu, float* __restrict__ act, int total4) {
    int i4 = blockIdx.x * blockDim.x + threadIdx.x;
    if (i4 >= total4) return;
    int i = i4 * 4;
    int p = i / I_DIM;
    int col = i - p * I_DIM;
    const float* base = gu + (size_t)p * (2 * I_DIM) + col;
    float4 gv = *(const float4*)(base);
    float4 uv = *(const float4*)(base + I_DIM);
    float4 r;
    r.x = gv.x / (1.f + expf(-gv.x)) * uv.x;
    r.y = gv.y / (1.f + expf(-gv.y)) * uv.y;
    r.z = gv.z / (1.f + expf(-gv.z)) * uv.z;
    r.w = gv.w / (1.f + expf(-gv.w)) * uv.w;
    *(float4*)(act + i) = r;
}

// ---------------- 4) tf32 GEMM: 128x128x32, register-staged double buffer ----------------
// A stored with k-permutation: raw col c = ks*8+tg+4q  ->  stored col ks*8 + 2*tg + q
// so fragment pairs (a0,a2) and (a1,a3) are contiguous float2 in smem.
struct SmemLayout {
    float As[2][128][40];   // 40-pad: <=2-way conflicts on LDS.64 frag reads
    float Bs[2][32][136];   // conflict-free LDS.32 frag reads
    int   sRow[128];
};
#define GEMM_SMEM_BYTES ((int)sizeof(SmemLayout))

__global__ __launch_bounds__(256, 2) void gemm_tf32_kernel(
    const float* __restrict__ A, const float* __restrict__ B, float* __restrict__ C,
    int lda, int ldb, int ldc, int K, int M,
    const int* __restrict__ permA, const int* __restrict__ permC,
    const int* __restrict__ goff, size_t bStride, int accumulate,
    const float* __restrict__ B2, int nSplit) {
    extern __shared__ char smem_raw[];
    SmemLayout& sm = *(SmemLayout*)smem_raw;

    int m_lo = 0, m_hi = M;
    if (goff) { m_lo = goff[blockIdx.z]; m_hi = goff[blockIdx.z + 1]; }
    int m_base = m_lo + blockIdx.y * 128;
    if (m_base >= m_hi) return;
    int m_cnt = m_hi - m_base;
    if (m_cnt > 128) m_cnt = 128;

    int n_base = blockIdx.x * 128;       // column in C
    const float* Bp = B + (size_t)blockIdx.z * bStride;
    int nb = n_base;                     // column in B
    if (B2 && nSplit > 0 && n_base >= nSplit) { Bp = B2; nb = n_base - nSplit; }

    int tid = threadIdx.x;
    for (int r = tid; r < 128; r += 256) {
        int row = 0;
        if (r < m_cnt) row = permA ? permA[m_base + r] : (m_base + r);
        sm.sRow[r] = row;
    }
    __syncthreads();

    int lane = tid & 31, wid = tid >> 5;
    int wm = wid >> 2, wn = wid & 3;     // 2 x 4 warp grid, warp tile 64x32
    int g = lane >> 2, tg = lane & 3;

    int ktiles = K >> 5;

    // --- staging helpers ---
    auto ldgA = [&](int kt, float4 v[4]) {
        int k0 = kt << 5;
#pragma unroll
        for (int j = 0; j < 4; ++j) {
            int lin = tid + j * 256;
            int r = lin >> 3, cc = (lin & 7) << 2;
            v[j] = *(const float4*)(A + (size_t)sm.sRow[r] * lda + k0 + cc);
        }
    };
    auto stsA = [&](int st, float4 v[4]) {
#pragma unroll
        for (int j = 0; j < 4; ++j) {
            int lin = tid + j * 256;
            int r = lin >> 3, cc = (lin & 7) << 2;
            int ks = cc >> 3, q = (cc >> 2) & 1;
            float* d = &sm.As[st][r][ks * 8 + q];     // elements go to +2*tg slots
            d[0] = f2tf32(v[j].x);
            d[2] = f2tf32(v[j].y);
            d[4] = f2tf32(v[j].z);
            d[6] = f2tf32(v[j].w);
        }
    };
    auto ldgB = [&](int kt, float4 v[4]) {
        int k0 = kt << 5;
#pragma unroll
        for (int j = 0; j < 4; ++j) {
            int lin = tid + j * 256;
            int r = lin >> 5, cc = (lin & 31) << 2;
            v[j] = *(const float4*)(Bp + (size_t)(k0 + r) * ldb + nb + cc);
        }
    };
    auto stsB = [&](int st, float4 v[4]) {
#pragma unroll
        for (int j = 0; j < 4; ++j) {
            int lin = tid + j * 256;
            int r = lin >> 5, cc = (lin & 31) << 2;
            float4 w;
            w.x = f2tf32(v[j].x); w.y = f2tf32(v[j].y);
            w.z = f2tf32(v[j].z); w.w = f2tf32(v[j].w);
            *(float4*)&sm.Bs[st][r][cc] = w;
        }
    };

    float cacc[4][4][4];
#pragma unroll
    for (int im = 0; im < 4; im++)
#pragma unroll
        for (int in = 0; in < 4; in++)
#pragma unroll
            for (int q = 0; q < 4; q++) cacc[im][in][q] = 0.f;

    // MMA over two ks steps from stage st
    auto mmaHalf = [&](int st, int ksBase) {
#pragma unroll
        for (int ks = ksBase; ks < ksBase + 2; ++ks) {
            int k0 = ks << 3;
            uint32_t af[4][4];
#pragma unroll
            for (int im = 0; im < 4; ++im) {
                int r0 = wm * 64 + im * 16;
                float2 u0 = *(const float2*)&sm.As[st][r0 + g][k0 + tg * 2];
                float2 u1 = *(const float2*)&sm.As[st][r0 + g + 8][k0 + tg * 2];
                af[im][0] = __float_as_uint(u0.x);
                af[im][1] = __float_as_uint(u1.x);
                af[im][2] = __float_as_uint(u0.y);
                af[im][3] = __float_as_uint(u1.y);
            }
            uint32_t bf[4][2];
#pragma unroll
            for (int in = 0; in < 4; ++in) {
                int col = wn * 32 + in * 8 + g;
                bf[in][0] = __float_as_uint(sm.Bs[st][k0 + tg][col]);
                bf[in][1] = __float_as_uint(sm.Bs[st][k0 + tg + 4][col]);
            }
#pragma unroll
            for (int im = 0; im < 4; ++im)
#pragma unroll
                for (int in = 0; in < 4; ++in)
                    mma_tf32(cacc[im][in], af[im][0], af[im][1], af[im][2], af[im][3],
                             bf[in][0], bf[in][1]);
        }
    };

    // prologue: stage tile 0 into buffer 0
    {
        float4 v[4];
        ldgA(0, v); stsA(0, v);
        ldgB(0, v); stsB(0, v);
    }

    for (int kt = 0; kt < ktiles; ++kt) {
        __syncthreads();                  // publish stage kt; orders reads of stn (iter kt-1) before its refill below
        int st = kt & 1, stn = st ^ 1;
        bool has_next = (kt + 1 < ktiles);
        float4 v[4];
        if (has_next) ldgA(kt + 1, v);    // DRAM latency hidden under ks0..1 MMAs
        mmaHalf(st, 0);
        if (has_next) stsA(stn, v);
        if (has_next) ldgB(kt + 1, v);    // hidden under ks2..3 MMAs
        mmaHalf(st, 2);
        if (has_next) stsB(stn, v);
    }

    // epilogue
#pragma unroll
    for (int im = 0; im < 4; ++im) {
#pragma unroll
        for (int half = 0; half < 2; ++half) {
            int r = wm * 64 + im * 16 + g + half * 8;
            if (r >= m_cnt) continue;
            int grow = permC ? permC[m_base + r] : (m_base + r);
            float* crow = C + (size_t)grow * ldc + n_base;
#pragma unroll
            for (int in = 0; in < 4; ++in) {
                int col = wn * 32 + in * 8 + tg * 2;
                float v0 = cacc[im][in][half * 2 + 0];
                float v1 = cacc[im][in][half * 2 + 1];
                if (accumulate) {
                    crow[col]     += v0;
                    crow[col + 1] += v1;
                } else {
                    *(float2*)(crow + col) = make_float2(v0, v1);
                }
            }
        }
    }
}

// ---------------- launch ----------------
extern "C" void kernel_launch(void* const* d_in, const int* in_sizes, int n_in,
                              void* d_out, int out_size) {
    const float* x   = (const float*)d_in[0];
    const float* rw  = (const float*)d_in[1];
    const float* gup = (const float*)d_in[2];
    const float* dwn = (const float*)d_in[3];
    const float* sgw = (const float*)d_in[4];
    const float* suw = (const float*)d_in[5];
    const float* sdw = (const float*)d_in[6];
    float* out = (float*)d_out;

    int T = in_sizes[0] / H_DIM;
    if (T > T_MAX) T = T_MAX;

    float *xs, *gu, *actS, *actR, *scores_scr;
    int *perm, *off;
    cudaGetSymbolAddress((void**)&xs, g_xs);
    cudaGetSymbolAddress((void**)&gu, g_gu);
    cudaGetSymbolAddress((void**)&actS, g_actS);
    cudaGetSymbolAddress((void**)&actR, g_actR);
    cudaGetSymbolAddress((void**)&perm, g_perm);
    cudaGetSymbolAddress((void**)&off, g_off);
    cudaGetSymbolAddress((void**)&scores_scr, g_scores_scratch);

    cudaFuncSetAttribute(gemm_tf32_kernel,
                         cudaFuncAttributeMaxDynamicSharedMemorySize, GEMM_SMEM_BYTES);

    float* scores_out = (out_size >= T * H_DIM + E_NUM * T) ? (out + (size_t)T * H_DIM)
                                                            : scores_scr;

    // 1) router + 2) grouping
    router_kernel<<<T, 256>>>(x, rw, scores_out, T);
    group_kernel<<<1, 1024>>>(T);

    // 3) shared gate+up fused into one launch over N=2I (B for cols<I, B2 for cols>=I)
    dim3 gS(2 * I_DIM / 128, T / 128, 1);
    gemm_tf32_kernel<<<gS, 256, GEMM_SMEM_BYTES>>>(x, sgw, gu, H_DIM, I_DIM, 2 * I_DIM, H_DIM, T,
                                  nullptr, nullptr, nullptr, 0, 0, suw, I_DIM);
    int tot4 = T * I_DIM / 4;
    swiglu_kernel<<<(tot4 + 255) / 256, 256>>>(gu, actS, tot4);

    // 4) routed grouped gate_up
    dim3 gR(2 * I_DIM / 128, (T + 127) / 128, E_NUM);
    gemm_tf32_kernel<<<gR, 256, GEMM_SMEM_BYTES>>>(xs, gup, gu, H_DIM, 2 * I_DIM, 2 * I_DIM, H_DIM, T,
                                  perm, nullptr, off, (size_t)H_DIM * 2 * I_DIM, 0, nullptr, 0);
    swiglu_kernel<<<(tot4 + 255) / 256, 256>>>(gu, actR, tot4);

    // 5) shared down -> out (write), routed down -> out (accumulate, scatter)
    dim3 gD(H_DIM / 128, T / 128, 1);
    gemm_tf32_kernel<<<gD, 256, GEMM_SMEM_BYTES>>>(actS, sdw, out, I_DIM, H_DIM, H_DIM, I_DIM, T,
                                  nullptr, nullptr, nullptr, 0, 0, nullptr, 0);
    dim3 gDR(H_DIM / 128, (T + 127) / 128, E_NUM);
    gemm_tf32_kernel<<<gDR, 256, GEMM_SMEM_BYTES>>>(actR, dwn, out, I_DIM, H_DIM, H_DIM, I_DIM, T,
                                   nullptr, perm, off, (size_t)I_DIM * H_DIM, 1, nullptr, 0);
}

// round 6
// speedup vs baseline: 1.0781x; 1.0781x over previous
#include <cuda_runtime.h>
#include <cstdint>
#include <math.h>

#define H_DIM 2048
#define I_DIM 4096
#define E_NUM 8
#define T_MAX 1024
#define STAGES 3

// ---------------- scratch (__device__ globals: allocation-free) ----------------
__device__ float g_xc[T_MAX * H_DIM];          // tf32-rounded, k-permuted x
__device__ float g_xs[T_MAX * H_DIM];          // tf32-rounded, k-permuted sc*x
__device__ float g_gu[T_MAX * 2 * I_DIM];      // gate_up staging (raw fp32)
__device__ float g_actS[T_MAX * I_DIM];        // shared swiglu acts (tf32, permuted)
__device__ float g_actR[T_MAX * I_DIM];        // routed swiglu acts (tf32, permuted)
__device__ int   g_eid[T_MAX];
__device__ int   g_perm[T_MAX];
__device__ int   g_off[E_NUM + 1];
__device__ float g_scores_scratch[E_NUM * T_MAX];

// ---------------- helpers ----------------
__device__ __forceinline__ float f2tf32(float x) {
    uint32_t u;
    asm("cvt.rna.tf32.f32 %0, %1;" : "=r"(u) : "f"(x));
    return __uint_as_float(u);
}

__device__ __forceinline__ void mma_tf32(float c[4],
                                         uint32_t a0, uint32_t a1, uint32_t a2, uint32_t a3,
                                         uint32_t b0, uint32_t b1) {
    asm volatile(
        "mma.sync.aligned.m16n8k8.row.col.f32.tf32.tf32.f32 "
        "{%0,%1,%2,%3}, {%4,%5,%6,%7}, {%8,%9}, {%0,%1,%2,%3};"
        : "+f"(c[0]), "+f"(c[1]), "+f"(c[2]), "+f"(c[3])
        : "r"(a0), "r"(a1), "r"(a2), "r"(a3), "r"(b0), "r"(b1));
}

__device__ __forceinline__ void cp16(void* smem, const void* g) {
    uint32_t s = (uint32_t)__cvta_generic_to_shared(smem);
    asm volatile("cp.async.cg.shared.global [%0], [%1], 16;" :: "r"(s), "l"(g));
}
__device__ __forceinline__ void cp_commit() {
    asm volatile("cp.async.commit_group;");
}
__device__ __forceinline__ void cp_wait1() {
    asm volatile("cp.async.wait_group 1;");
}

// permute 8 raw values into k-permuted order: stored[2t+q] = raw[t+4q]
__device__ __forceinline__ void store_perm8(float* dst, const float r[8]) {
    float4 a = make_float4(r[0], r[4], r[1], r[5]);
    float4 b = make_float4(r[2], r[6], r[3], r[7]);
    *(float4*)(dst)     = a;
    *(float4*)(dst + 4) = b;
}

// ---------------- 1) router: fp32 logits, top-1, sigmoid; writes permuted tf32 xc/xs ----------------
__global__ void router_kernel(const float* __restrict__ x, const float* __restrict__ rw,
                              float* __restrict__ scores_out, int T) {
    int t = blockIdx.x;
    int tid = threadIdx.x;
    __shared__ float s[256 * 8];
    __shared__ float sc_sh;

    int c0 = tid * 8;                      // this thread's 8 contiguous columns
    float xv[8];
    {
        float4 a = *(const float4*)(x + (size_t)t * H_DIM + c0);
        float4 b = *(const float4*)(x + (size_t)t * H_DIM + c0 + 4);
        xv[0] = a.x; xv[1] = a.y; xv[2] = a.z; xv[3] = a.w;
        xv[4] = b.x; xv[5] = b.y; xv[6] = b.z; xv[7] = b.w;
    }
    float acc[8];
#pragma unroll
    for (int e = 0; e < 8; e++) acc[e] = 0.f;
#pragma unroll
    for (int j = 0; j < 8; j++) {
        float v = xv[j];
        const float4* wp = (const float4*)(rw + (size_t)(c0 + j) * 8);
        float4 w0 = wp[0], w1 = wp[1];
        acc[0] += v * w0.x; acc[1] += v * w0.y; acc[2] += v * w0.z; acc[3] += v * w0.w;
        acc[4] += v * w1.x; acc[5] += v * w1.y; acc[6] += v * w1.z; acc[7] += v * w1.w;
    }
#pragma unroll
    for (int e = 0; e < 8; e++) s[tid * 8 + e] = acc[e];
    __syncthreads();
    for (int str = 128; str > 0; str >>= 1) {
        if (tid < str) {
#pragma unroll
            for (int e = 0; e < 8; e++) s[tid * 8 + e] += s[(tid + str) * 8 + e];
        }
        __syncthreads();
    }
    if (tid == 0) {
        int best = 0;
        float bv = s[0];
#pragma unroll
        for (int e = 1; e < 8; e++) {
            if (s[e] > bv) { bv = s[e]; best = e; }
        }
        float sc = 1.f / (1.f + expf(-bv));
        g_eid[t] = best;
#pragma unroll
        for (int e = 0; e < 8; e++)
            scores_out[(size_t)e * T + t] = (e == best) ? sc : 0.f;
        sc_sh = sc;
    }
    __syncthreads();
    float sc = sc_sh;
    float rc[8], rs[8];
#pragma unroll
    for (int j = 0; j < 8; j++) {
        rc[j] = f2tf32(xv[j]);
        rs[j] = f2tf32(sc * xv[j]);
    }
    store_perm8(&g_xc[(size_t)t * H_DIM + c0], rc);
    store_perm8(&g_xs[(size_t)t * H_DIM + c0], rs);
}

// ---------------- 2) deterministic stable grouping by expert ----------------
__global__ void group_kernel(int T) {
    int t = threadIdx.x;
    __shared__ int wcnt[32][8];
    __shared__ int woff[32][8];
    __shared__ int eoff[9];
    __shared__ int ecnt[8];
    if (t < 256) ((int*)wcnt)[t] = 0;
    __syncthreads();
    int e = (t < T) ? g_eid[t] : -1;
    unsigned mask = __match_any_sync(0xffffffffu, e);
    unsigned lanebit = 1u << (t & 31);
    int rank = __popc(mask & (lanebit - 1u));
    int w = t >> 5;
    if (e >= 0 && rank == 0) wcnt[w][e] = __popc(mask);
    __syncthreads();
    if (t < 8) {
        int run = 0;
        for (int ww = 0; ww < 32; ww++) { woff[ww][t] = run; run += wcnt[ww][t]; }
        ecnt[t] = run;
    }
    __syncthreads();
    if (t == 0) {
        int run = 0;
        for (int ee = 0; ee < 8; ee++) { eoff[ee] = run; run += ecnt[ee]; }
        eoff[8] = run;
    }
    __syncthreads();
    if (e >= 0) g_perm[eoff[e] + woff[w][e] + rank] = t;
    if (t < 9) g_off[t] = eoff[t];
}

// ---------------- 3) swiglu: act = tf32(silu(gate)*up), k-permuted store ----------------
__global__ void swiglu_kernel(const float* __restrict__ gu, float* __restrict__ act, int total8) {
    int i8 = blockIdx.x * blockDim.x + threadIdx.x;
    if (i8 >= total8) return;
    int i = i8 * 8;
    int p = i / I_DIM;
    int col = i - p * I_DIM;
    const float* base = gu + (size_t)p * (2 * I_DIM) + col;
    float4 g0 = *(const float4*)(base);
    float4 g1 = *(const float4*)(base + 4);
    float4 u0 = *(const float4*)(base + I_DIM);
    float4 u1 = *(const float4*)(base + I_DIM + 4);
    float gg[8] = {g0.x, g0.y, g0.z, g0.w, g1.x, g1.y, g1.z, g1.w};
    float uu[8] = {u0.x, u0.y, u0.z, u0.w, u1.x, u1.y, u1.z, u1.w};
    float r[8];
#pragma unroll
    for (int j = 0; j < 8; j++)
        r[j] = f2tf32(gg[j] / (1.f + expf(-gg[j])) * uu[j]);
    store_perm8(act + (size_t)p * I_DIM + col, r);
}

// ---------------- 4) tf32 GEMM: 128x128x32, 3-stage cp.async pipeline ----------------
// A arrives pre-converted (tf32) and pre-permuted: frag pairs read as LDS.64, no CVT.
struct SmemLayout {
    float As[STAGES][128][36];   // 36-pad (16B-aligned rows): <=2-way conflict on LDS.64
    float Bs[STAGES][32][136];   // conflict-free LDS.32 frag reads
    int   sRow[128];
};
#define GEMM_SMEM_BYTES ((int)sizeof(SmemLayout))

__global__ __launch_bounds__(256, 2) void gemm_tf32_kernel(
    const float* __restrict__ A, const float* __restrict__ B, float* __restrict__ C,
    int lda, int ldb, int ldc, int K, int M,
    const int* __restrict__ permA, const int* __restrict__ permC,
    const int* __restrict__ goff, size_t bStride, int accumulate,
    const float* __restrict__ B2, int nSplit) {
    extern __shared__ char smem_raw[];
    SmemLayout& sm = *(SmemLayout*)smem_raw;

    int m_lo = 0, m_hi = M;
    if (goff) { m_lo = goff[blockIdx.z]; m_hi = goff[blockIdx.z + 1]; }
    int m_base = m_lo + blockIdx.y * 128;
    if (m_base >= m_hi) return;
    int m_cnt = m_hi - m_base;
    if (m_cnt > 128) m_cnt = 128;

    int n_base = blockIdx.x * 128;       // column in C
    const float* Bp = B + (size_t)blockIdx.z * bStride;
    int nb = n_base;                     // column in B
    if (B2 && nSplit > 0 && n_base >= nSplit) { Bp = B2; nb = n_base - nSplit; }

    int tid = threadIdx.x;
    for (int r = tid; r < 128; r += 256) {
        int row = 0;
        if (r < m_cnt) row = permA ? permA[m_base + r] : (m_base + r);
        sm.sRow[r] = row;   // clamped: out-of-range rows load data that is discarded
    }
    __syncthreads();

    int lane = tid & 31, wid = tid >> 5;
    int wm = wid >> 2, wn = wid & 3;     // 2 x 4 warp grid, warp tile 64x32
    int g = lane >> 2, tg = lane & 3;

    int ktiles = K >> 5;

    auto loadTile = [&](int kt, int st) {
        int k0 = kt << 5;
#pragma unroll
        for (int j = 0; j < 4; ++j) {
            int lin = tid + j * 256;
            int r = lin >> 3, cc = (lin & 7) << 2;
            cp16(&sm.As[st][r][cc], A + (size_t)sm.sRow[r] * lda + k0 + cc);
        }
#pragma unroll
        for (int j = 0; j < 4; ++j) {
            int lin = tid + j * 256;
            int r = lin >> 5, cc = (lin & 31) << 2;
            cp16(&sm.Bs[st][r][cc], Bp + (size_t)(k0 + r) * ldb + nb + cc);
        }
    };

    float cacc[4][4][4];
#pragma unroll
    for (int im = 0; im < 4; im++)
#pragma unroll
        for (int in = 0; in < 4; in++)
#pragma unroll
            for (int q = 0; q < 4; q++) cacc[im][in][q] = 0.f;

    // prologue: stages 0,1
    loadTile(0, 0); cp_commit();
    if (ktiles > 1) loadTile(1, 1);
    cp_commit();

    for (int kt = 0; kt < ktiles; ++kt) {
        cp_wait1();              // group kt drained -> stage kt%3 ready
        __syncthreads();
        if (kt + 2 < ktiles) loadTile(kt + 2, (kt + 2) % STAGES);
        cp_commit();             // commit every iter (possibly empty) to keep count

        int st = kt % STAGES;
#pragma unroll
        for (int ks = 0; ks < 4; ++ks) {
            int k0 = ks << 3;
            uint32_t af[4][4];
#pragma unroll
            for (int im = 0; im < 4; ++im) {
                int r0 = wm * 64 + im * 16;
                float2 u0 = *(const float2*)&sm.As[st][r0 + g][k0 + tg * 2];
                float2 u1 = *(const float2*)&sm.As[st][r0 + g + 8][k0 + tg * 2];
                af[im][0] = __float_as_uint(u0.x);   // raw col k0+tg
                af[im][1] = __float_as_uint(u1.x);
                af[im][2] = __float_as_uint(u0.y);   // raw col k0+tg+4
                af[im][3] = __float_as_uint(u1.y);
            }
            uint32_t bf[4][2];
#pragma unroll
            for (int in = 0; in < 4; ++in) {
                int col = wn * 32 + in * 8 + g;
                bf[in][0] = __float_as_uint(f2tf32(sm.Bs[st][k0 + tg][col]));
                bf[in][1] = __float_as_uint(f2tf32(sm.Bs[st][k0 + tg + 4][col]));
            }
#pragma unroll
            for (int im = 0; im < 4; ++im)
#pragma unroll
                for (int in = 0; in < 4; ++in)
                    mma_tf32(cacc[im][in], af[im][0], af[im][1], af[im][2], af[im][3],
                             bf[in][0], bf[in][1]);
        }
        __syncthreads();   // stage kt fully consumed before refill at iter kt+1
    }

    // epilogue: c0=(g,2t) c1=(g,2t+1) c2=(g+8,2t) c3=(g+8,2t+1)
#pragma unroll
    for (int im = 0; im < 4; ++im) {
#pragma unroll
        for (int half = 0; half < 2; ++half) {
            int r = wm * 64 + im * 16 + g + half * 8;
            if (r >= m_cnt) continue;
            int grow = permC ? permC[m_base + r] : (m_base + r);
            float* crow = C + (size_t)grow * ldc + n_base;
#pragma unroll
            for (int in = 0; in < 4; ++in) {
                int col = wn * 32 + in * 8 + tg * 2;
                float v0 = cacc[im][in][half * 2 + 0];
                float v1 = cacc[im][in][half * 2 + 1];
                if (accumulate) {
                    crow[col]     += v0;
                    crow[col + 1] += v1;
                } else {
                    *(float2*)(crow + col) = make_float2(v0, v1);
                }
            }
        }
    }
}

// ---------------- launch ----------------
extern "C" void kernel_launch(void* const* d_in, const int* in_sizes, int n_in,
                              void* d_out, int out_size) {
    const float* x   = (const float*)d_in[0];
    const float* rw  = (const float*)d_in[1];
    const float* gup = (const float*)d_in[2];
    const float* dwn = (const float*)d_in[3];
    const float* sgw = (const float*)d_in[4];
    const float* suw = (const float*)d_in[5];
    const float* sdw = (const float*)d_in[6];
    float* out = (float*)d_out;

    int T = in_sizes[0] / H_DIM;
    if (T > T_MAX) T = T_MAX;

    float *xc, *xs, *gu, *actS, *actR, *scores_scr;
    int *perm, *off;
    cudaGetSymbolAddress((void**)&xc, g_xc);
    cudaGetSymbolAddress((void**)&xs, g_xs);
    cudaGetSymbolAddress((void**)&gu, g_gu);
    cudaGetSymbolAddress((void**)&actS, g_actS);
    cudaGetSymbolAddress((void**)&actR, g_actR);
    cudaGetSymbolAddress((void**)&perm, g_perm);
    cudaGetSymbolAddress((void**)&off, g_off);
    cudaGetSymbolAddress((void**)&scores_scr, g_scores_scratch);

    cudaFuncSetAttribute(gemm_tf32_kernel,
                         cudaFuncAttributeMaxDynamicSharedMemorySize, GEMM_SMEM_BYTES);

    float* scores_out = (out_size >= T * H_DIM + E_NUM * T) ? (out + (size_t)T * H_DIM)
                                                            : scores_scr;

    // 1) router (fp32 exact top-1) + permuted tf32 xc/xs; 2) grouping
    router_kernel<<<T, 256>>>(x, rw, scores_out, T);
    group_kernel<<<1, 1024>>>(T);

    // 3) shared gate+up fused into one launch over N=2I (sgw cols<I, suw cols>=I)
    dim3 gS(2 * I_DIM / 128, T / 128, 1);
    gemm_tf32_kernel<<<gS, 256, GEMM_SMEM_BYTES>>>(xc, sgw, gu, H_DIM, I_DIM, 2 * I_DIM, H_DIM, T,
                                  nullptr, nullptr, nullptr, 0, 0, suw, I_DIM);
    int tot8 = T * I_DIM / 8;
    swiglu_kernel<<<(tot8 + 255) / 256, 256>>>(gu, actS, tot8);

    // 4) routed grouped gate_up (gather rows by perm, write sorted order)
    dim3 gR(2 * I_DIM / 128, (T + 127) / 128, E_NUM);
    gemm_tf32_kernel<<<gR, 256, GEMM_SMEM_BYTES>>>(xs, gup, gu, H_DIM, 2 * I_DIM, 2 * I_DIM, H_DIM, T,
                                  perm, nullptr, off, (size_t)H_DIM * 2 * I_DIM, 0, nullptr, 0);
    swiglu_kernel<<<(tot8 + 255) / 256, 256>>>(gu, actR, tot8);

    // 5) shared down -> out (write), routed down -> out (accumulate, scatter)
    dim3 gD(H_DIM / 128, T / 128, 1);
    gemm_tf32_kernel<<<gD, 256, GEMM_SMEM_BYTES>>>(actS, sdw, out, I_DIM, H_DIM, H_DIM, I_DIM, T,
                                  nullptr, nullptr, nullptr, 0, 0, nullptr, 0);
    dim3 gDR(H_DIM / 128, (T + 127) / 128, E_NUM);
    gemm_tf32_kernel<<<gDR, 256, GEMM_SMEM_BYTES>>>(actR, dwn, out, I_DIM, H_DIM, H_DIM, I_DIM, T,
                                   nullptr, perm, off, (size_t)I_DIM * H_DIM, 1, nullptr, 0);
}